// round 11
// baseline (speedup 1.0000x reference)
#include <cuda_runtime.h>
#include <cuda_bf16.h>

// ProdLayer: out[i] = prod_{j : csr[j]==i} x[ptrs[j]], empty segments -> 0.
// csr sorted ascending, csr[E-1] == S-1 => contiguous runs.
//
// R7: 16 edges per thread (4x int4 loads each for csr/ptrs). Per-thread
// suffix-run products P[m] resolve in-thread run heads in registers.
// Warp-level segmented suffix scan combines trailing runs across threads;
// at most one serial continuation per warp for the run spilling past it.

#define EPT 16   // edges per thread

__global__ void __launch_bounds__(256)
prod_seg16_kernel(const float* __restrict__ x,
                  const int*   __restrict__ ptrs,
                  const int*   __restrict__ csr,
                  float*       __restrict__ out,
                  int E)
{
    const unsigned FULL = 0xffffffffu;
    int t    = blockIdx.x * blockDim.x + threadIdx.x;
    int lane = threadIdx.x & 31;
    int b    = t * EPT;                      // first edge of this thread
    bool valid = (b < E);

    int   K[EPT];
    float X[EPT];
    #pragma unroll
    for (int m = 0; m < EPT; ++m) { K[m] = -2; X[m] = 1.0f; }

    if (valid) {
        if (b + EPT - 1 < E) {
            #pragma unroll
            for (int q = 0; q < EPT / 4; ++q) {
                int4 kk = *reinterpret_cast<const int4*>(csr  + b + 4 * q);
                int4 pp = *reinterpret_cast<const int4*>(ptrs + b + 4 * q);
                K[4*q+0]=kk.x; K[4*q+1]=kk.y; K[4*q+2]=kk.z; K[4*q+3]=kk.w;
                X[4*q+0]=__ldg(&x[pp.x]); X[4*q+1]=__ldg(&x[pp.y]);
                X[4*q+2]=__ldg(&x[pp.z]); X[4*q+3]=__ldg(&x[pp.w]);
            }
        } else {
            #pragma unroll
            for (int m = 0; m < EPT; ++m) {
                if (b + m < E) {
                    K[m] = __ldg(&csr[b + m]);
                    X[m] = __ldg(&x[__ldg(&ptrs[b + m])]);
                }
            }
        }
    }

    // Key of last valid edge in this thread (-2 if none).
    int kt = -2;
    #pragma unroll
    for (int m = 0; m < EPT; ++m) if (K[m] != -2) kt = K[m];

    // Suffix-run products within the thread: P[m] = prod of X over m's run
    // starting at m. Sentinel slots have X=1 so they are inert.
    float P[EPT];
    P[EPT - 1] = X[EPT - 1];
    #pragma unroll
    for (int m = EPT - 2; m >= 0; --m)
        P[m] = X[m] * ((K[m + 1] == K[m]) ? P[m + 1] : 1.0f);

    // s = product of trailing run = P[first index whose key == kt].
    float s = 1.0f;
    #pragma unroll
    for (int m = EPT - 1; m >= 0; --m) if (K[m] == kt) s = P[m];

    // g = prefix-run product for key K[0] (sortedness: direct compares).
    float g = X[0];
    #pragma unroll
    for (int m = 1; m < EPT; ++m) g *= (K[m] == K[0]) ? X[m] : 1.0f;

    // prev = key of edge b-1.
    int prev = __shfl_up_sync(FULL, kt, 1);
    if (lane == 0) prev = (b > 0) ? __ldg(&csr[b - 1]) : -1;

    // Warp segmented suffix scan over thread aggregates.
    int   K0 = K[0];
    float V = s, G = g;
    #pragma unroll
    for (int d = 1; d < 32; d <<= 1) {
        int   kd = __shfl_down_sync(FULL, K0, d);
        float Gd = __shfl_down_sync(FULL, G,  d);
        bool src = (lane + d) < 32;
        if (src && kd == kt) V *= Gd;     // trailing run extends into t+d
        if (src && kd == K0) G *= Gd;     // prefix run spans the window
    }

    int kLast = __shfl_sync(FULL, kt, 31);

    // Cross-warp continuation: only the head of the warp-trailing run.
    if (valid && (K0 != kt || prev != kt) && kt == kLast) {
        int e = b - lane * EPT + 32 * EPT;   // first edge after this warp
        while (e < E && __ldg(&csr[e]) == kt) {
            V *= __ldg(&x[__ldg(&ptrs[e])]);
            ++e;
        }
    }

    if (!valid) return;

    // Emit: for each in-thread run head, zero-fill the empty-id gap then
    // write the run product (trailing run uses scanned V).
    int p = prev;
    #pragma unroll
    for (int m = 0; m < EPT; ++m) {
        int km = K[m];
        if (km >= 0 && km != p) {
            for (int i = p + 1; i < km; ++i) out[i] = 0.0f;
            out[km] = (km == kt) ? V : P[m];
        }
        if (km >= 0) p = km;
    }
}

extern "C" void kernel_launch(void* const* d_in, const int* in_sizes, int n_in,
                              void* d_out, int out_size)
{
    const float* x    = (const float*)d_in[0];
    const int*   ptrs = (const int*)  d_in[1];
    const int*   csr  = (const int*)  d_in[2];
    float*       out  = (float*)      d_out;

    int E = in_sizes[1];
    int nthreads = (E + EPT - 1) / EPT;
    int block = 256;
    int grid  = (nthreads + block - 1) / block;
    prod_seg16_kernel<<<grid, block>>>(x, ptrs, csr, out, E);
}

// round 13
// speedup vs baseline: 1.0974x; 1.0974x over previous
#include <cuda_runtime.h>
#include <cuda_bf16.h>

// ProdLayer: out[i] = prod_{j : csr[j]==i} x[ptrs[j]], empty segments -> 0.
// csr sorted ascending, csr[E-1] == S-1 => contiguous runs.
//
// R8: EPT=8 (best known) + persistent grid-stride loop. Warps iterate over
// 256-edge warp-tiles; the loop keeps gathers continuously in flight and
// removes per-block cold-start bubbles. csr/ptrs streamed with __ldcs
// (evict-first) to protect x's L2 residency.

#define EPT 8

__global__ void __launch_bounds__(256)
prod_seg8p_kernel(const float* __restrict__ x,
                  const int*   __restrict__ ptrs,
                  const int*   __restrict__ csr,
                  float*       __restrict__ out,
                  int E)
{
    const unsigned FULL = 0xffffffffu;
    int lane   = threadIdx.x & 31;
    int stride = gridDim.x * blockDim.x * EPT;

    for (int b = (blockIdx.x * blockDim.x + threadIdx.x) * EPT;
         b - lane * EPT < E;                     // loop while the WARP has work
         b += stride)
    {
        bool valid = (b < E);

        int   K[EPT];
        float X[EPT];
        #pragma unroll
        for (int m = 0; m < EPT; ++m) { K[m] = -2; X[m] = 1.0f; }

        if (valid) {
            if (b + EPT - 1 < E) {
                int4 ka = __ldcs(reinterpret_cast<const int4*>(csr  + b));
                int4 kb = __ldcs(reinterpret_cast<const int4*>(csr  + b + 4));
                int4 pa = __ldcs(reinterpret_cast<const int4*>(ptrs + b));
                int4 pb = __ldcs(reinterpret_cast<const int4*>(ptrs + b + 4));
                K[0]=ka.x; K[1]=ka.y; K[2]=ka.z; K[3]=ka.w;
                K[4]=kb.x; K[5]=kb.y; K[6]=kb.z; K[7]=kb.w;
                X[0]=__ldg(&x[pa.x]); X[1]=__ldg(&x[pa.y]);
                X[2]=__ldg(&x[pa.z]); X[3]=__ldg(&x[pa.w]);
                X[4]=__ldg(&x[pb.x]); X[5]=__ldg(&x[pb.y]);
                X[6]=__ldg(&x[pb.z]); X[7]=__ldg(&x[pb.w]);
            } else {
                #pragma unroll
                for (int m = 0; m < EPT; ++m) {
                    if (b + m < E) {
                        K[m] = __ldg(&csr[b + m]);
                        X[m] = __ldg(&x[__ldg(&ptrs[b + m])]);
                    }
                }
            }
        }

        // Key of last valid edge in this thread (-2 if none).
        int kt = -2;
        #pragma unroll
        for (int m = 0; m < EPT; ++m) if (K[m] != -2) kt = K[m];

        // Suffix-run products: P[m] = prod of X over m's run starting at m.
        float P[EPT];
        P[EPT - 1] = X[EPT - 1];
        #pragma unroll
        for (int m = EPT - 2; m >= 0; --m)
            P[m] = X[m] * ((K[m + 1] == K[m]) ? P[m + 1] : 1.0f);

        // s = product of trailing run = P[first index whose key == kt].
        float s = 1.0f;
        #pragma unroll
        for (int m = EPT - 1; m >= 0; --m) if (K[m] == kt) s = P[m];

        // g = prefix-run product for key K[0].
        float g = X[0];
        #pragma unroll
        for (int m = 1; m < EPT; ++m) g *= (K[m] == K[0]) ? X[m] : 1.0f;

        // prev = key of edge b-1.
        int prev = __shfl_up_sync(FULL, kt, 1);
        if (lane == 0) prev = (b > 0) ? __ldg(&csr[b - 1]) : -1;

        // Warp segmented suffix scan over thread aggregates.
        int   K0 = K[0];
        float V = s, G = g;
        #pragma unroll
        for (int d = 1; d < 32; d <<= 1) {
            int   kd = __shfl_down_sync(FULL, K0, d);
            float Gd = __shfl_down_sync(FULL, G,  d);
            bool src = (lane + d) < 32;
            if (src && kd == kt) V *= Gd;     // trailing run extends into t+d
            if (src && kd == K0) G *= Gd;     // prefix run spans the window
        }

        int kLast = __shfl_sync(FULL, kt, 31);

        // Cross-warp continuation: only the head of the warp-trailing run.
        if (valid && (K0 != kt || prev != kt) && kt == kLast) {
            int e = b - lane * EPT + 32 * EPT;   // first edge after this warp-tile
            while (e < E && __ldg(&csr[e]) == kt) {
                V *= __ldg(&x[__ldg(&ptrs[e])]);
                ++e;
            }
        }

        if (!valid) continue;

        // Emit: zero-fill empty-id gaps, write run products.
        int p = prev;
        #pragma unroll
        for (int m = 0; m < EPT; ++m) {
            int km = K[m];
            if (km >= 0 && km != p) {
                for (int i = p + 1; i < km; ++i) out[i] = 0.0f;
                out[km] = (km == kt) ? V : P[m];
            }
            if (km >= 0) p = km;
        }
    }
}

extern "C" void kernel_launch(void* const* d_in, const int* in_sizes, int n_in,
                              void* d_out, int out_size)
{
    const float* x    = (const float*)d_in[0];
    const int*   ptrs = (const int*)  d_in[1];
    const int*   csr  = (const int*)  d_in[2];
    float*       out  = (float*)      d_out;

    int E = in_sizes[1];

    // Persistent-ish: ~8 blocks per SM on 152-SM GB300; grid-stride handles
    // any remainder and any actual residency.
    int block = 256;
    int grid  = 152 * 8;
    prod_seg8p_kernel<<<grid, block>>>(x, ptrs, csr, out, E);
}